// round 8
// baseline (speedup 1.0000x reference)
#include <cuda_runtime.h>
#include <cuda_bf16.h>
#include <cstdint>

// LinearRationalSpline forward — persistent TMA pipeline, TRIPLE-buffered.
// inputs:  [16384, 64] f32     (N = 1048576)
// params:  [16384, 64, 63] f32 (w[16], h[16], d[15], lam[16])
// out:     [2*N] f32
//
// TILE=64, TPB=64, 3 pipeline stages per block (49.2 KB smem) -> 4 resident
// blocks/SM. While a block computes tile t, tiles t+1 and t+2 stream in
// (~131 KB outstanding DRAM bytes per SM, vs ~98 KB with double buffering
// which sat exactly at the Little's-law knee and capped DRAM at 77%).

#define TPB   64
#define TILE  64
#define NBINS 16
#define STAGES 3
#define BLOCKS_PER_SM 4
#define NUM_SMS 148

#define STAGE_FLOATS (TILE * 63)
#define PARAMS_BYTES (STAGE_FLOATS * 4)          // 16128
#define X_BYTES      (TILE * 4)                  // 256
#define STAGE_BYTES  (PARAMS_BYTES + X_BYTES)    // 16384
#define BUF_OFF      64                          // 3 mbarriers in [0,24)
#define SMEM_TOTAL   (BUF_OFF + STAGES * STAGE_BYTES) // 49216

__device__ __forceinline__ uint32_t smem_u32(const void* p) {
    uint32_t a;
    asm("{ .reg .u64 t; cvta.to.shared.u64 t, %1; cvt.u32.u64 %0, t; }"
        : "=r"(a) : "l"(p));
    return a;
}
__device__ __forceinline__ void mbar_init(uint32_t mbar, uint32_t cnt) {
    asm volatile("mbarrier.init.shared.b64 [%0], %1;" :: "r"(mbar), "r"(cnt) : "memory");
}
__device__ __forceinline__ void mbar_expect_tx(uint32_t mbar, uint32_t bytes) {
    asm volatile("mbarrier.arrive.expect_tx.shared.b64 _, [%0], %1;"
                 :: "r"(mbar), "r"(bytes) : "memory");
}
__device__ __forceinline__ void mbar_wait(uint32_t mbar, uint32_t parity) {
    asm volatile(
        "{\n\t"
        ".reg .pred P1;\n\t"
        "WAIT_%=:\n\t"
        "mbarrier.try_wait.parity.acquire.cta.shared::cta.b64 P1, [%0], %1, 0x989680;\n\t"
        "@P1 bra.uni DONE_%=;\n\t"
        "bra.uni WAIT_%=;\n\t"
        "DONE_%=:\n\t"
        "}" :: "r"(mbar), "r"(parity) : "memory");
}
__device__ __forceinline__ void bulk_g2s(uint32_t dst, const void* src,
                                         uint32_t bytes, uint32_t mbar) {
    asm volatile(
        "cp.async.bulk.shared::cluster.global.mbarrier::complete_tx::bytes "
        "[%0], [%1], %2, [%3];"
        :: "r"(dst), "l"(src), "r"(bytes), "r"(mbar) : "memory");
}
__device__ __forceinline__ void fence_async() {
    asm volatile("fence.proxy.async.shared::cta;" ::: "memory");
}

__device__ __forceinline__ float softplus_f(float v) {
    return fmaxf(v, 0.0f) + __logf(1.0f + __expf(-fabsf(v)));
}

__device__ __forceinline__ void issue_tile(uint32_t sbase, int stg,
                                           const float* params, const float* inputs,
                                           long long tile) {
    uint32_t mbar = sbase + stg * 8;
    uint32_t dst  = sbase + BUF_OFF + (uint32_t)stg * STAGE_BYTES;
    mbar_expect_tx(mbar, STAGE_BYTES);
    bulk_g2s(dst, params + tile * STAGE_FLOATS, PARAMS_BYTES, mbar);
    bulk_g2s(dst + PARAMS_BYTES, inputs + tile * TILE, X_BYTES, mbar);
}

// one element's spline math (p = 63 params in smem, stride-63 conflict-free)
__device__ __forceinline__ void spline_one(const float* __restrict__ p, float x,
                                           float& outv, float& lad) {
    constexpr float BOUND = 3.0f;
    constexpr float MBW   = 0.001f;
    constexpr float MBH   = 0.001f;
    constexpr float MIND  = 0.001f;
    constexpr float MINL  = 0.025f;
    constexpr float EPSV  = 1e-6f;

    // widths / heights softmax cumsums (no max-subtract: |p| small, f32 safe)
    float cw[NBINS], ch[NBINS];
    {
        float s = 0.0f;
        #pragma unroll
        for (int i = 0; i < NBINS; i++) { s += __expf(p[i]); cw[i] = s; }
    }
    {
        float s = 0.0f;
        #pragma unroll
        for (int i = 0; i < NBINS; i++) { s += __expf(p[16 + i]); ch[i] = s; }
    }
    const float Aw = 6.0f * (1.0f - 16.0f * MBW) * __frcp_rn(cw[NBINS - 1]);
    const float Ah = 6.0f * (1.0f - 16.0f * MBH) * __frcp_rn(ch[NBINS - 1]);

    // fused bin search: width knot predicate also selects height knots
    int cnt = 0;
    float cumw  = -BOUND, wnext = BOUND;
    float ya    = -BOUND, ykn   = BOUND;
    bool found = false;
    #pragma unroll
    for (int i = 1; i <= 15; i++) {
        const float kv = fmaf(Aw, cw[i - 1], 6.0f * MBW * (float)i - BOUND);
        const float hv = fmaf(Ah, ch[i - 1], 6.0f * MBH * (float)i - BOUND);
        const bool c = (kv + EPSV) <= x;
        cnt  += c ? 1 : 0;
        cumw  = c ? kv : cumw;
        ya    = c ? hv : ya;
        if (!c && !found) { wnext = kv; ykn = hv; found = true; }
    }
    cnt += ((BOUND + EPSV) <= x) ? 1 : 0;
    const int b = cnt > 15 ? 15 : cnt;

    const float input_widths  = wnext - cumw;
    const float input_heights = ykn - ya;
    const float yb = input_heights + ya;

    // derivatives + lambda (dynamic LDS)
    const float d0r  = p[32 + (b > 0  ? b - 1 : 0)];
    const float d1r  = p[32 + (b < 15 ? b     : 14)];
    const float lraw = p[47 + b];

    const float d0 = (b == 0)  ? (1.0f - MIND) : (MIND + softplus_f(d0r));
    const float d1 = (b == 15) ? (1.0f - MIND) : (MIND + softplus_f(d1r));

    const float sig = __frcp_rn(1.0f + __expf(-lraw));
    const float lam = fmaf(1.0f - 2.0f * MINL, sig, MINL);

    // rational spline
    const float wbv = __fsqrt_rn(__fdividef(d0, d1));
    const float lwb = lam * wbv;
    const float delta = __fdividef(input_heights, input_widths);
    const float wc = __fdividef(fmaf(lam, d0, (wbv - lwb) * d1), delta);
    const float l1 = 1.0f - lam;
    const float yc = __fdividef(lwb * yb + l1 * ya, l1 + lwb);

    const float theta = __fdividef(x - cumw, input_widths);
    const bool ind = theta <= lam;
    const float ltheta = lam - theta;

    const float wcyc = wc * yc;
    const float wcyctheta = wcyc * theta;
    const float num = ind ? fmaf(ya, ltheta, wcyctheta)
                          : (wcyc - wcyctheta) - (wbv * yb) * ltheta;
    const float wctheta = wc * theta;
    const float den = ind ? (wctheta + ltheta)
                          : (wc - wctheta) - wbv * ltheta;
    outv = __fdividef(num, den);

    // logabsdet = log( wc*sel / (w * den^2) )
    const float sel = ind ? lam * (yc - ya) : (wbv - lwb) * (yb - yc);
    lad = __logf(__fdividef(wc * sel, input_widths * (den * den)));
}

__global__ __launch_bounds__(TPB)
void lrs_kernel(const float* __restrict__ inputs,
                const float* __restrict__ params,
                float* __restrict__ out,
                int N, int numTiles)
{
    constexpr float BOUND = 3.0f;

    extern __shared__ char smem[];
    const uint32_t sbase = smem_u32(smem);
    const int tid = threadIdx.x;

    if (tid == 0) {
        #pragma unroll
        for (int i = 0; i < STAGES; i++) mbar_init(sbase + i * 8, 1);
        fence_async();
    }
    __syncthreads();

    const long long step = gridDim.x;

    // prologue: fill all 3 stages
    if (tid == 0) {
        #pragma unroll
        for (int s = 0; s < STAGES; s++) {
            long long t = blockIdx.x + (long long)s * step;
            if (t < numTiles && (t + 1) * TILE <= N)
                issue_tile(sbase, s, params, inputs, t);
        }
    }

    int phases[STAGES] = {0, 0, 0};
    int stg = 0;

    for (long long tile = blockIdx.x; tile < numTiles; tile += step) {
        const long long e0 = tile * TILE;
        const int elems = (N - e0) < TILE ? (int)(N - e0) : TILE;
        float* bufp = (float*)(smem + BUF_OFF + (size_t)stg * STAGE_BYTES);
        float* bufx = bufp + STAGE_FLOATS;

        if (elems == TILE) {
            mbar_wait(sbase + stg * 8, phases[stg]);
            phases[stg] ^= 1;
        } else {
            // partial tail tile (never hit: N % 64 == 0, kept for safety)
            for (int i = tid; i < elems * 63; i += TPB)
                bufp[i] = params[e0 * 63 + i];
            for (int i = tid; i < elems; i += TPB)
                bufx[i] = inputs[e0 + i];
            __syncthreads();
        }

        if (tid < elems) {
            const float x = bufx[tid];
            float outv, lad;
            spline_one(bufp + tid * 63, x, outv, lad);

            const bool outside = (x < -BOUND) || (x > BOUND);
            const int e = (int)e0 + tid;
            out[e]     = outside ? x    : outv;
            out[N + e] = outside ? 0.0f : lad;
        }

        __syncthreads();   // all warps done reading this stage

        // refill this stage with tile + STAGES*step
        long long nt = tile + (long long)STAGES * step;
        if (tid == 0 && nt < numTiles && (nt + 1) * TILE <= N) {
            fence_async();
            issue_tile(sbase, stg, params, inputs, nt);
        }
        stg = (stg + 1 == STAGES) ? 0 : stg + 1;
    }
}

extern "C" void kernel_launch(void* const* d_in, const int* in_sizes, int n_in,
                              void* d_out, int out_size) {
    const float* inputs = (const float*)d_in[0];
    const float* params = (const float*)d_in[1];
    float* out = (float*)d_out;
    const int N = in_sizes[0];
    const int numTiles = (N + TILE - 1) / TILE;

    cudaFuncSetAttribute(lrs_kernel,
                         cudaFuncAttributeMaxDynamicSharedMemorySize, SMEM_TOTAL);

    int grid = NUM_SMS * BLOCKS_PER_SM;    // one resident wave
    if (grid > numTiles) grid = numTiles;
    lrs_kernel<<<grid, TPB, SMEM_TOTAL>>>(inputs, params, out, N, numTiles);
}

// round 9
// speedup vs baseline: 1.0212x; 1.0212x over previous
#include <cuda_runtime.h>
#include <cuda_bf16.h>
#include <cstdint>

// LinearRationalSpline forward — persistent single-warp TMA streams.
// inputs:  [16384, 64] f32     (N = 1048576)
// params:  [16384, 64, 63] f32 (w[16], h[16], d[15], lam[16])
// out:     [2*N] f32
//
// TPB=32, TILE=32: each block is ONE warp owning a double-buffered
// cp.async.bulk stream (8064 B params/tile; x prefetched via LDG 2 tiles
// ahead). 16.2 KB smem/block -> 13-14 resident blocks/SM = 13-14 warps AND
// 13-14 independent pipeline streams per SM (prior rounds capped at 12 and
// showed DRAM% tracks warp count). Grid = SMs x occupancy, one exact wave.

#define TPB   32
#define TILE  32
#define NBINS 16
#define STAGES 2

#define STAGE_FLOATS (TILE * 63)                 // 2016
#define STAGE_BYTES  (STAGE_FLOATS * 4)          // 8064
#define BUF_OFF      64                          // 2 mbarriers in [0,16)
#define SMEM_TOTAL   (BUF_OFF + STAGES * STAGE_BYTES)  // 16192

__device__ __forceinline__ uint32_t smem_u32(const void* p) {
    uint32_t a;
    asm("{ .reg .u64 t; cvta.to.shared.u64 t, %1; cvt.u32.u64 %0, t; }"
        : "=r"(a) : "l"(p));
    return a;
}
__device__ __forceinline__ void mbar_init(uint32_t mbar, uint32_t cnt) {
    asm volatile("mbarrier.init.shared.b64 [%0], %1;" :: "r"(mbar), "r"(cnt) : "memory");
}
__device__ __forceinline__ void mbar_expect_tx(uint32_t mbar, uint32_t bytes) {
    asm volatile("mbarrier.arrive.expect_tx.shared.b64 _, [%0], %1;"
                 :: "r"(mbar), "r"(bytes) : "memory");
}
__device__ __forceinline__ void mbar_wait(uint32_t mbar, uint32_t parity) {
    asm volatile(
        "{\n\t"
        ".reg .pred P1;\n\t"
        "WAIT_%=:\n\t"
        "mbarrier.try_wait.parity.acquire.cta.shared::cta.b64 P1, [%0], %1, 0x989680;\n\t"
        "@P1 bra.uni DONE_%=;\n\t"
        "bra.uni WAIT_%=;\n\t"
        "DONE_%=:\n\t"
        "}" :: "r"(mbar), "r"(parity) : "memory");
}
__device__ __forceinline__ void bulk_g2s(uint32_t dst, const void* src,
                                         uint32_t bytes, uint32_t mbar) {
    asm volatile(
        "cp.async.bulk.shared::cluster.global.mbarrier::complete_tx::bytes "
        "[%0], [%1], %2, [%3];"
        :: "r"(dst), "l"(src), "r"(bytes), "r"(mbar) : "memory");
}
__device__ __forceinline__ void fence_async() {
    asm volatile("fence.proxy.async.shared::cta;" ::: "memory");
}
__device__ __forceinline__ float rcp_approx(float x) {
    float r; asm("rcp.approx.f32 %0, %1;" : "=f"(r) : "f"(x)); return r;
}
__device__ __forceinline__ float sqrt_approx(float x) {
    float r; asm("sqrt.approx.f32 %0, %1;" : "=f"(r) : "f"(x)); return r;
}
__device__ __forceinline__ float softplus_f(float v) {
    return fmaxf(v, 0.0f) + __logf(1.0f + __expf(-fabsf(v)));
}

__device__ __forceinline__ void issue_tile(uint32_t sbase, int stg,
                                           const float* params, long long tile) {
    uint32_t mbar = sbase + stg * 8;
    uint32_t dst  = sbase + BUF_OFF + (uint32_t)stg * STAGE_BYTES;
    mbar_expect_tx(mbar, STAGE_BYTES);
    bulk_g2s(dst, params + tile * STAGE_FLOATS, STAGE_BYTES, mbar);
}

// one element's spline math (p = 63 params in smem, stride-63 conflict-free)
__device__ __forceinline__ void spline_one(const float* __restrict__ p, float x,
                                           float& outv, float& lad) {
    constexpr float BOUND = 3.0f;
    constexpr float MBW   = 0.001f;
    constexpr float MBH   = 0.001f;
    constexpr float MIND  = 0.001f;
    constexpr float MINL  = 0.025f;
    constexpr float EPSV  = 1e-6f;

    // softmax cumsums (no max-subtract: |p| small, f32 exp safe)
    float cw[NBINS], ch[NBINS];
    {
        float s = 0.0f;
        #pragma unroll
        for (int i = 0; i < NBINS; i++) { s += __expf(p[i]); cw[i] = s; }
    }
    {
        float s = 0.0f;
        #pragma unroll
        for (int i = 0; i < NBINS; i++) { s += __expf(p[16 + i]); ch[i] = s; }
    }
    const float Aw = (6.0f * (1.0f - 16.0f * MBW)) * rcp_approx(cw[NBINS - 1]);
    const float Ah = (6.0f * (1.0f - 16.0f * MBH)) * rcp_approx(ch[NBINS - 1]);

    // fused bin search (width predicate also selects height knots)
    const float xm = x - EPSV;           // kv + eps <= x  ->  kv <= xm
    int cnt = 0;
    float cumw  = -BOUND, wnext = BOUND;
    float ya    = -BOUND, ykn   = BOUND;
    bool found = false;
    #pragma unroll
    for (int i = 1; i <= 15; i++) {
        const float kv = fmaf(Aw, cw[i - 1], 6.0f * MBW * (float)i - BOUND);
        const float hv = fmaf(Ah, ch[i - 1], 6.0f * MBH * (float)i - BOUND);
        const bool c = kv <= xm;
        cnt  += c ? 1 : 0;
        cumw  = c ? kv : cumw;
        ya    = c ? hv : ya;
        if (!c && !found) { wnext = kv; ykn = hv; found = true; }
    }
    cnt += (BOUND <= xm) ? 1 : 0;
    const int b = cnt > 15 ? 15 : cnt;

    const float input_widths  = wnext - cumw;
    const float input_heights = ykn - ya;
    const float yb = input_heights + ya;

    // derivatives + lambda (dynamic LDS)
    const float d0r  = p[32 + (b > 0  ? b - 1 : 0)];
    const float d1r  = p[32 + (b < 15 ? b     : 14)];
    const float lraw = p[47 + b];

    const float d0 = (b == 0)  ? (1.0f - MIND) : (MIND + softplus_f(d0r));
    const float d1 = (b == 15) ? (1.0f - MIND) : (MIND + softplus_f(d1r));

    const float sig = rcp_approx(1.0f + __expf(-lraw));
    const float lam = fmaf(1.0f - 2.0f * MINL, sig, MINL);

    // rational spline
    const float wbv = sqrt_approx(__fdividef(d0, d1));
    const float lwb = lam * wbv;
    const float delta = __fdividef(input_heights, input_widths);
    const float wc = __fdividef(fmaf(lam, d0, (wbv - lwb) * d1), delta);
    const float l1 = 1.0f - lam;
    const float yc = __fdividef(lwb * yb + l1 * ya, l1 + lwb);

    const float theta = __fdividef(x - cumw, input_widths);
    const bool ind = theta <= lam;
    const float ltheta = lam - theta;

    const float wcyc = wc * yc;
    const float wcyctheta = wcyc * theta;
    const float num = ind ? fmaf(ya, ltheta, wcyctheta)
                          : (wcyc - wcyctheta) - (wbv * yb) * ltheta;
    const float wctheta = wc * theta;
    const float den = ind ? (wctheta + ltheta)
                          : (wc - wctheta) - wbv * ltheta;
    outv = __fdividef(num, den);

    // logabsdet = log( wc*sel / (w * den^2) )
    const float sel = ind ? lam * (yc - ya) : (wbv - lwb) * (yb - yc);
    lad = __logf(__fdividef(wc * sel, input_widths * (den * den)));
}

__global__ __launch_bounds__(TPB)
void lrs_kernel(const float* __restrict__ inputs,
                const float* __restrict__ params,
                float* __restrict__ out,
                int N, int numTiles)
{
    constexpr float BOUND = 3.0f;

    extern __shared__ char smem[];
    const uint32_t sbase = smem_u32(smem);
    const int tid = threadIdx.x;

    if (tid == 0) {
        mbar_init(sbase + 0, 1);
        mbar_init(sbase + 8, 1);
        fence_async();
    }
    __syncwarp();

    const long long step = gridDim.x;

    // prologue: prefetch both stages + x two tiles ahead
    if (tid == 0) {
        long long t0 = blockIdx.x;
        long long t1 = blockIdx.x + step;
        if (t0 < numTiles && (t0 + 1) * TILE <= N) issue_tile(sbase, 0, params, t0);
        if (t1 < numTiles && (t1 + 1) * TILE <= N) issue_tile(sbase, 1, params, t1);
    }
    float xq0 = 0.0f, xq1 = 0.0f;
    {
        long long t0 = blockIdx.x;
        long long t1 = blockIdx.x + step;
        if (t0 < numTiles) {
            long long i = t0 * TILE + tid; if (i >= N) i = N - 1;
            xq0 = __ldg(inputs + i);
        }
        if (t1 < numTiles) {
            long long i = t1 * TILE + tid; if (i >= N) i = N - 1;
            xq1 = __ldg(inputs + i);
        }
    }

    int ph0 = 0, ph1 = 0;
    int stg = 0;

    for (long long tile = blockIdx.x; tile < numTiles; tile += step) {
        const long long e0 = tile * TILE;
        const int elems = (N - e0) < TILE ? (int)(N - e0) : TILE;
        float* bufp = (float*)(smem + BUF_OFF + (size_t)stg * STAGE_BYTES);

        const float x = xq0;
        xq0 = xq1;
        // prefetch x for tile + 2*step now (consumed 2 iterations later)
        {
            long long nt = tile + 2 * step;
            if (nt < numTiles) {
                long long i = nt * TILE + tid; if (i >= N) i = N - 1;
                xq1 = __ldg(inputs + i);
            }
        }

        if (elems == TILE) {
            if (stg == 0) { mbar_wait(sbase + 0, ph0); ph0 ^= 1; }
            else          { mbar_wait(sbase + 8, ph1); ph1 ^= 1; }
        } else {
            // partial tail tile (not hit for N % 32 == 0; kept for safety)
            for (int i = tid; i < elems * 63; i += TPB)
                bufp[i] = params[e0 * 63 + i];
            __syncwarp();
        }

        if (tid < elems) {
            float outv, lad;
            spline_one(bufp + tid * 63, x, outv, lad);

            const bool outside = (x < -BOUND) || (x > BOUND);
            const int e = (int)e0 + tid;
            out[e]     = outside ? x    : outv;
            out[N + e] = outside ? 0.0f : lad;
        }

        __syncwarp();   // warp done reading this stage

        long long nt = tile + (long long)STAGES * step;
        if (tid == 0 && nt < numTiles && (nt + 1) * TILE <= N) {
            fence_async();
            issue_tile(sbase, stg, params, nt);
        }
        stg ^= 1;
    }
}

extern "C" void kernel_launch(void* const* d_in, const int* in_sizes, int n_in,
                              void* d_out, int out_size) {
    const float* inputs = (const float*)d_in[0];
    const float* params = (const float*)d_in[1];
    float* out = (float*)d_out;
    const int N = in_sizes[0];
    const int numTiles = (N + TILE - 1) / TILE;

    cudaFuncSetAttribute(lrs_kernel,
                         cudaFuncAttributeMaxDynamicSharedMemorySize, SMEM_TOTAL);

    // exactly one resident wave: SMs x max resident blocks
    int dev = 0, nsm = 148;
    cudaGetDevice(&dev);
    cudaDeviceGetAttribute(&nsm, cudaDevAttrMultiProcessorCount, dev);
    int maxb = 1;
    cudaOccupancyMaxActiveBlocksPerMultiprocessor(&maxb, lrs_kernel, TPB, SMEM_TOTAL);
    if (maxb < 1) maxb = 1;

    long long grid = (long long)nsm * maxb;
    if (grid > numTiles) grid = numTiles;
    lrs_kernel<<<(int)grid, TPB, SMEM_TOTAL>>>(inputs, params, out, N, numTiles);
}

// round 10
// speedup vs baseline: 1.0635x; 1.0414x over previous
#include <cuda_runtime.h>
#include <cuda_bf16.h>
#include <cstdint>

// LinearRationalSpline forward — persistent TMA pipeline, slim stages.
// inputs:  [16384, 64] f32     (N = 1048576)
// params:  [16384, 64, 63] f32 (w[16], h[16], d[15], lam[16])
// out:     [2*N] f32
//
// R6 config (TILE=64, TPB=64, double-buffered 16.1 KB bulk copies — best
// observed) with the x-vector moved out of the TMA stage into an LDG
// prefetch queue: stage drops to 16128 B -> 32.3 KB/block -> 7 resident
// blocks/SM (14 warps, 7 streams) instead of 6 (12 warps). Grid sized via
// occupancy API x real SM count (152 on GB300) for one uniform wave.

#define TPB   64
#define TILE  64
#define NBINS 16
#define STAGES 2

#define STAGE_FLOATS (TILE * 63)                 // 4032
#define STAGE_BYTES  (STAGE_FLOATS * 4)          // 16128
#define BUF_OFF      64                          // 2 mbarriers in [0,16)
#define SMEM_TOTAL   (BUF_OFF + STAGES * STAGE_BYTES)  // 32320

__device__ __forceinline__ uint32_t smem_u32(const void* p) {
    uint32_t a;
    asm("{ .reg .u64 t; cvta.to.shared.u64 t, %1; cvt.u32.u64 %0, t; }"
        : "=r"(a) : "l"(p));
    return a;
}
__device__ __forceinline__ void mbar_init(uint32_t mbar, uint32_t cnt) {
    asm volatile("mbarrier.init.shared.b64 [%0], %1;" :: "r"(mbar), "r"(cnt) : "memory");
}
__device__ __forceinline__ void mbar_expect_tx(uint32_t mbar, uint32_t bytes) {
    asm volatile("mbarrier.arrive.expect_tx.shared.b64 _, [%0], %1;"
                 :: "r"(mbar), "r"(bytes) : "memory");
}
__device__ __forceinline__ void mbar_wait(uint32_t mbar, uint32_t parity) {
    asm volatile(
        "{\n\t"
        ".reg .pred P1;\n\t"
        "WAIT_%=:\n\t"
        "mbarrier.try_wait.parity.acquire.cta.shared::cta.b64 P1, [%0], %1, 0x989680;\n\t"
        "@P1 bra.uni DONE_%=;\n\t"
        "bra.uni WAIT_%=;\n\t"
        "DONE_%=:\n\t"
        "}" :: "r"(mbar), "r"(parity) : "memory");
}
__device__ __forceinline__ void bulk_g2s(uint32_t dst, const void* src,
                                         uint32_t bytes, uint32_t mbar) {
    asm volatile(
        "cp.async.bulk.shared::cluster.global.mbarrier::complete_tx::bytes "
        "[%0], [%1], %2, [%3];"
        :: "r"(dst), "l"(src), "r"(bytes), "r"(mbar) : "memory");
}
__device__ __forceinline__ void fence_async() {
    asm volatile("fence.proxy.async.shared::cta;" ::: "memory");
}
__device__ __forceinline__ float rcp_approx(float x) {
    float r; asm("rcp.approx.f32 %0, %1;" : "=f"(r) : "f"(x)); return r;
}
__device__ __forceinline__ float sqrt_approx(float x) {
    float r; asm("sqrt.approx.f32 %0, %1;" : "=f"(r) : "f"(x)); return r;
}
__device__ __forceinline__ float softplus_f(float v) {
    return fmaxf(v, 0.0f) + __logf(1.0f + __expf(-fabsf(v)));
}

__device__ __forceinline__ void issue_tile(uint32_t sbase, int stg,
                                           const float* params, long long tile) {
    uint32_t mbar = sbase + stg * 8;
    uint32_t dst  = sbase + BUF_OFF + (uint32_t)stg * STAGE_BYTES;
    mbar_expect_tx(mbar, STAGE_BYTES);
    bulk_g2s(dst, params + tile * STAGE_FLOATS, STAGE_BYTES, mbar);
}

// one element's spline math (p = 63 params in smem, stride-63 conflict-free)
__device__ __forceinline__ void spline_one(const float* __restrict__ p, float x,
                                           float& outv, float& lad) {
    constexpr float BOUND = 3.0f;
    constexpr float MBW   = 0.001f;
    constexpr float MBH   = 0.001f;
    constexpr float MIND  = 0.001f;
    constexpr float MINL  = 0.025f;
    constexpr float EPSV  = 1e-6f;

    // softmax cumsums (no max-subtract: |p| small, f32 exp safe)
    float cw[NBINS], ch[NBINS];
    {
        float s = 0.0f;
        #pragma unroll
        for (int i = 0; i < NBINS; i++) { s += __expf(p[i]); cw[i] = s; }
    }
    {
        float s = 0.0f;
        #pragma unroll
        for (int i = 0; i < NBINS; i++) { s += __expf(p[16 + i]); ch[i] = s; }
    }
    const float Aw = (6.0f * (1.0f - 16.0f * MBW)) * rcp_approx(cw[NBINS - 1]);
    const float Ah = (6.0f * (1.0f - 16.0f * MBH)) * rcp_approx(ch[NBINS - 1]);

    // fused bin search (width predicate also selects height knots)
    const float xm = x - EPSV;           // kv + eps <= x  ->  kv <= xm
    int cnt = 0;
    float cumw  = -BOUND, wnext = BOUND;
    float ya    = -BOUND, ykn   = BOUND;
    bool found = false;
    #pragma unroll
    for (int i = 1; i <= 15; i++) {
        const float kv = fmaf(Aw, cw[i - 1], 6.0f * MBW * (float)i - BOUND);
        const float hv = fmaf(Ah, ch[i - 1], 6.0f * MBH * (float)i - BOUND);
        const bool c = kv <= xm;
        cnt  += c ? 1 : 0;
        cumw  = c ? kv : cumw;
        ya    = c ? hv : ya;
        if (!c && !found) { wnext = kv; ykn = hv; found = true; }
    }
    cnt += (BOUND <= xm) ? 1 : 0;
    const int b = cnt > 15 ? 15 : cnt;

    const float input_widths  = wnext - cumw;
    const float input_heights = ykn - ya;
    const float yb = input_heights + ya;

    // derivatives + lambda (dynamic LDS)
    const float d0r  = p[32 + (b > 0  ? b - 1 : 0)];
    const float d1r  = p[32 + (b < 15 ? b     : 14)];
    const float lraw = p[47 + b];

    const float d0 = (b == 0)  ? (1.0f - MIND) : (MIND + softplus_f(d0r));
    const float d1 = (b == 15) ? (1.0f - MIND) : (MIND + softplus_f(d1r));

    const float sig = rcp_approx(1.0f + __expf(-lraw));
    const float lam = fmaf(1.0f - 2.0f * MINL, sig, MINL);

    // rational spline
    const float wbv = sqrt_approx(__fdividef(d0, d1));
    const float lwb = lam * wbv;
    const float delta = __fdividef(input_heights, input_widths);
    const float wc = __fdividef(fmaf(lam, d0, (wbv - lwb) * d1), delta);
    const float l1 = 1.0f - lam;
    const float yc = __fdividef(lwb * yb + l1 * ya, l1 + lwb);

    const float theta = __fdividef(x - cumw, input_widths);
    const bool ind = theta <= lam;
    const float ltheta = lam - theta;

    const float wcyc = wc * yc;
    const float wcyctheta = wcyc * theta;
    const float num = ind ? fmaf(ya, ltheta, wcyctheta)
                          : (wcyc - wcyctheta) - (wbv * yb) * ltheta;
    const float wctheta = wc * theta;
    const float den = ind ? (wctheta + ltheta)
                          : (wc - wctheta) - wbv * ltheta;
    outv = __fdividef(num, den);

    // logabsdet = log( wc*sel / (w * den^2) )
    const float sel = ind ? lam * (yc - ya) : (wbv - lwb) * (yb - yc);
    lad = __logf(__fdividef(wc * sel, input_widths * (den * den)));
}

__global__ __launch_bounds__(TPB)
void lrs_kernel(const float* __restrict__ inputs,
                const float* __restrict__ params,
                float* __restrict__ out,
                int N, int numTiles)
{
    constexpr float BOUND = 3.0f;

    extern __shared__ char smem[];
    const uint32_t sbase = smem_u32(smem);
    const int tid = threadIdx.x;

    if (tid == 0) {
        mbar_init(sbase + 0, 1);
        mbar_init(sbase + 8, 1);
        fence_async();
    }
    __syncthreads();

    const long long step = gridDim.x;

    // prologue: prefetch both param stages + x two tiles ahead (LDG queue)
    if (tid == 0) {
        long long t0 = blockIdx.x;
        long long t1 = blockIdx.x + step;
        if (t0 < numTiles && (t0 + 1) * TILE <= N) issue_tile(sbase, 0, params, t0);
        if (t1 < numTiles && (t1 + 1) * TILE <= N) issue_tile(sbase, 1, params, t1);
    }
    float xq0 = 0.0f, xq1 = 0.0f;
    {
        long long t0 = blockIdx.x;
        long long t1 = blockIdx.x + step;
        if (t0 < numTiles) {
            long long i = t0 * TILE + tid; if (i >= N) i = N - 1;
            xq0 = __ldg(inputs + i);
        }
        if (t1 < numTiles) {
            long long i = t1 * TILE + tid; if (i >= N) i = N - 1;
            xq1 = __ldg(inputs + i);
        }
    }

    int ph0 = 0, ph1 = 0;
    int stg = 0;

    for (long long tile = blockIdx.x; tile < numTiles; tile += step) {
        const long long e0 = tile * TILE;
        const int elems = (N - e0) < TILE ? (int)(N - e0) : TILE;
        float* bufp = (float*)(smem + BUF_OFF + (size_t)stg * STAGE_BYTES);

        const float x = xq0;
        xq0 = xq1;
        // prefetch x for tile + 2*step (consumed two iterations later)
        {
            long long nt = tile + 2 * step;
            if (nt < numTiles) {
                long long i = nt * TILE + tid; if (i >= N) i = N - 1;
                xq1 = __ldg(inputs + i);
            }
        }

        if (elems == TILE) {
            if (stg == 0) { mbar_wait(sbase + 0, ph0); ph0 ^= 1; }
            else          { mbar_wait(sbase + 8, ph1); ph1 ^= 1; }
        } else {
            // partial tail tile (never hit for N % 64 == 0; kept for safety)
            for (int i = tid; i < elems * 63; i += TPB)
                bufp[i] = params[e0 * 63 + i];
            __syncthreads();
        }

        if (tid < elems) {
            float outv, lad;
            spline_one(bufp + tid * 63, x, outv, lad);

            const bool outside = (x < -BOUND) || (x > BOUND);
            const int e = (int)e0 + tid;
            out[e]     = outside ? x    : outv;
            out[N + e] = outside ? 0.0f : lad;
        }

        __syncthreads();   // both warps done reading this stage

        long long nt = tile + (long long)STAGES * step;
        if (tid == 0 && nt < numTiles && (nt + 1) * TILE <= N) {
            fence_async();
            issue_tile(sbase, stg, params, nt);
        }
        stg ^= 1;
    }
}

extern "C" void kernel_launch(void* const* d_in, const int* in_sizes, int n_in,
                              void* d_out, int out_size) {
    const float* inputs = (const float*)d_in[0];
    const float* params = (const float*)d_in[1];
    float* out = (float*)d_out;
    const int N = in_sizes[0];
    const int numTiles = (N + TILE - 1) / TILE;

    cudaFuncSetAttribute(lrs_kernel,
                         cudaFuncAttributeMaxDynamicSharedMemorySize, SMEM_TOTAL);

    // one resident wave: real SM count x max resident blocks (target 7/SM)
    int dev = 0, nsm = 148;
    cudaGetDevice(&dev);
    cudaDeviceGetAttribute(&nsm, cudaDevAttrMultiProcessorCount, dev);
    int maxb = 1;
    cudaOccupancyMaxActiveBlocksPerMultiprocessor(&maxb, lrs_kernel, TPB, SMEM_TOTAL);
    if (maxb < 1) maxb = 1;

    long long grid = (long long)nsm * maxb;
    if (grid > numTiles) grid = numTiles;
    lrs_kernel<<<(int)grid, TPB, SMEM_TOTAL>>>(inputs, params, out, N, numTiles);
}